// round 5
// baseline (speedup 1.0000x reference)
#include <cuda_runtime.h>
#include <cuda_bf16.h>
#include <cstdint>

#define N_NODES 50000
#define N_EDGES 600000
#define D_FEAT  128
#define OUT_DIM 128
#define K_DIM   256   // 2 * D_FEAT

#define SCAN_BLK 512
#define N_SCAN_BLKS ((N_NODES + SCAN_BLK - 1) / SCAN_BLK)   // 98

// ---------------------------------------------------------------------------
// Scratch (static device globals; no allocation anywhere)
// ---------------------------------------------------------------------------
__device__ int g_cnt_i [N_NODES];
__device__ int g_cursor[N_NODES];
__device__ int g_off   [N_NODES];
__device__ int g_btot  [N_SCAN_BLKS];
__device__ int g_boff  [N_SCAN_BLKS];
__device__ int g_eid   [N_EDGES];
__device__ __align__(16) float g_agg[N_NODES * D_FEAT];             // 25.6 MB
// Pre-swizzled bf16 hi/lo images of W, layout [K][N] with 16B-unit swizzle
__device__ __align__(16) __nv_bfloat16 g_Whi_img[K_DIM * OUT_DIM];  // 64 KB
__device__ __align__(16) __nv_bfloat16 g_Wlo_img[K_DIM * OUT_DIM];  // 64 KB

// ---------------------------------------------------------------------------
// Swizzles: XOR the 16B-unit index with (row & 7) so ldmatrix's 8 row-lanes
// hit 8 distinct banks (row strides 512B / 256B are 128B-aligned -> would
// otherwise be 8-way conflicts).
// ---------------------------------------------------------------------------
__host__ __device__ __forceinline__ uint32_t swzX(int row, int kb) {  // X: 512B rows
    return (uint32_t)(row * 512) +
           (uint32_t)((kb & 15) | ((((kb >> 4) ^ (row & 7)) & 31) << 4));
}
__host__ __device__ __forceinline__ uint32_t swzW(int k, int nb) {    // W: 256B rows
    return (uint32_t)(k * 256) +
           (uint32_t)((nb & 15) | ((((nb >> 4) ^ (k & 7)) & 15) << 4));
}

// ---------------------------------------------------------------------------
// Small kernels: counters / histogram / scan / id-scatter
// ---------------------------------------------------------------------------
__global__ void zero_counters_kernel() {
    int i = blockIdx.x * blockDim.x + threadIdx.x;
    if (i < N_NODES) { g_cnt_i[i] = 0; g_cursor[i] = 0; }
}

__global__ void count_kernel(const int* __restrict__ src_idx) {
    int e = blockIdx.x * blockDim.x + threadIdx.x;
    if (e < N_EDGES) atomicAdd(&g_cnt_i[src_idx[e]], 1);
}

__global__ __launch_bounds__(SCAN_BLK)
void scan_partial_kernel() {
    __shared__ int sh[SCAN_BLK];
    const int tid = threadIdx.x;
    const int i   = blockIdx.x * SCAN_BLK + tid;
    const int v   = (i < N_NODES) ? g_cnt_i[i] : 0;
    sh[tid] = v;
    __syncthreads();
    #pragma unroll
    for (int d = 1; d < SCAN_BLK; d <<= 1) {
        int t = (tid >= d) ? sh[tid - d] : 0;
        __syncthreads();
        sh[tid] += t;
        __syncthreads();
    }
    if (i < N_NODES) g_off[i] = sh[tid] - v;   // exclusive within block
    if (tid == SCAN_BLK - 1) g_btot[blockIdx.x] = sh[tid];
}

__global__ __launch_bounds__(128)
void scan_btot_kernel() {
    __shared__ int sh[128];
    const int t = threadIdx.x;
    const int v = (t < N_SCAN_BLKS) ? g_btot[t] : 0;
    sh[t] = v;
    __syncthreads();
    #pragma unroll
    for (int d = 1; d < 128; d <<= 1) {
        int x = (t >= d) ? sh[t - d] : 0;
        __syncthreads();
        sh[t] += x;
        __syncthreads();
    }
    if (t < N_SCAN_BLKS) g_boff[t] = sh[t] - v;   // exclusive
}

__global__ void scatter_ids_kernel(const int* __restrict__ src_idx) {
    int e = blockIdx.x * blockDim.x + threadIdx.x;
    if (e < N_EDGES) {
        const int s = src_idx[e];
        const int pos = g_off[s] + g_boff[s >> 9] + atomicAdd(&g_cursor[s], 1);
        g_eid[pos] = e;
    }
}

// ---------------------------------------------------------------------------
// Gather-reduce: one warp per node, lane owns a float4 column chunk.
// ---------------------------------------------------------------------------
__global__ __launch_bounds__(256)
void gather_kernel(const float* __restrict__ nbr_feat) {
    const int warp = (blockIdx.x * blockDim.x + threadIdx.x) >> 5;
    const int lane = threadIdx.x & 31;
    if (warp >= N_NODES) return;

    const int base = g_off[warp] + g_boff[warp >> 9];
    const int deg  = g_cnt_i[warp];

    const float4* nb4 = reinterpret_cast<const float4*>(nbr_feat);
    float4 acc = make_float4(0.f, 0.f, 0.f, 0.f);

    int i = 0;
    for (; i + 2 <= deg; i += 2) {
        const int e0 = g_eid[base + i];
        const int e1 = g_eid[base + i + 1];
        const float4 v0 = nb4[(size_t)e0 * (D_FEAT / 4) + lane];
        const float4 v1 = nb4[(size_t)e1 * (D_FEAT / 4) + lane];
        acc.x += v0.x + v1.x;  acc.y += v0.y + v1.y;
        acc.z += v0.z + v1.z;  acc.w += v0.w + v1.w;
    }
    if (i < deg) {
        const int e = g_eid[base + i];
        const float4 v = nb4[(size_t)e * (D_FEAT / 4) + lane];
        acc.x += v.x; acc.y += v.y; acc.z += v.z; acc.w += v.w;
    }

    const float s = (deg > 0) ? (1.0f / (float)deg) : 0.0f;
    acc.x *= s; acc.y *= s; acc.z *= s; acc.w *= s;
    reinterpret_cast<float4*>(g_agg)[(size_t)warp * (D_FEAT / 4) + lane] = acc;
}

// ---------------------------------------------------------------------------
// W pre-conversion: fp32 -> bf16 hi/lo, written at swizzled [K][N] offsets.
// ---------------------------------------------------------------------------
__global__ void wconv_kernel(const float* __restrict__ W) {
    int idx = blockIdx.x * blockDim.x + threadIdx.x;
    if (idx >= K_DIM * OUT_DIM) return;
    const int k = idx >> 7;    // W row-major [K][N]
    const int n = idx & 127;
    const float w = W[idx];
    const __nv_bfloat16 hi = __float2bfloat16(w);
    const __nv_bfloat16 lo = __float2bfloat16(w - __bfloat162float(hi));
    const uint32_t off = swzW(k, n * 2);
    *reinterpret_cast<__nv_bfloat16*>(reinterpret_cast<char*>(g_Whi_img) + off) = hi;
    *reinterpret_cast<__nv_bfloat16*>(reinterpret_cast<char*>(g_Wlo_img) + off) = lo;
}

// ---------------------------------------------------------------------------
// mma.sync GEMM (base-ISA tensor path; tcgen05 is not available because the
// harness targets compute_103 without the 'a' feature set).
//
// Per block: 64 rows x 128 cols, K=256, bf16 hi/lo split (err ~2^-16).
// 8 warps = 4 m-tiles (16 rows) x 2 n-halves (64 cols). Per warp per k-step:
// 2 ldmatrix.x4 (A hi/lo) + 8 ldmatrix.x4.trans (W hi/lo, 4 ntile-pairs) +
// 24 mma.m16n8k16. Accumulators stay in registers across k.
// ---------------------------------------------------------------------------
#define SM_XHI 0
#define SM_XLO 32768
#define SM_WHI 65536
#define SM_WLO 131072
#define SM_TOT 196608

__device__ __forceinline__ uint32_t smem_u32(const void* p) {
    uint32_t a;
    asm("{ .reg .u64 t; cvta.to.shared.u64 t, %1; cvt.u32.u64 %0, t; }"
        : "=r"(a) : "l"(p));
    return a;
}

__device__ __forceinline__ void ldsm_x4(uint32_t addr, uint32_t r[4]) {
    asm volatile("ldmatrix.sync.aligned.m8n8.x4.shared.b16 {%0,%1,%2,%3}, [%4];"
                 : "=r"(r[0]), "=r"(r[1]), "=r"(r[2]), "=r"(r[3]) : "r"(addr));
}
__device__ __forceinline__ void ldsm_x4_t(uint32_t addr, uint32_t r[4]) {
    asm volatile("ldmatrix.sync.aligned.m8n8.x4.trans.shared.b16 {%0,%1,%2,%3}, [%4];"
                 : "=r"(r[0]), "=r"(r[1]), "=r"(r[2]), "=r"(r[3]) : "r"(addr));
}
__device__ __forceinline__ void mma_16816(float c[4], const uint32_t a[4],
                                          uint32_t b0, uint32_t b1) {
    asm volatile(
        "mma.sync.aligned.m16n8k16.row.col.f32.bf16.bf16.f32 "
        "{%0,%1,%2,%3}, {%4,%5,%6,%7}, {%8,%9}, {%0,%1,%2,%3};"
        : "+f"(c[0]), "+f"(c[1]), "+f"(c[2]), "+f"(c[3])
        : "r"(a[0]), "r"(a[1]), "r"(a[2]), "r"(a[3]), "r"(b0), "r"(b1));
}

__global__ __launch_bounds__(256, 1)
void gemm_mma_kernel(const float* __restrict__ self_feat,
                     float*       __restrict__ out) {
    extern __shared__ char smem[];
    const uint32_t sbase = smem_u32(smem);
    const int tid  = threadIdx.x;
    const int wid  = tid >> 5;
    const int lane = tid & 31;
    const int n0b  = blockIdx.x * 64;     // first node row of this block

    // --- Copy pre-swizzled W images into smem (raw float4 copies) ---
    {
        const float4* hi4 = reinterpret_cast<const float4*>(g_Whi_img);
        const float4* lo4 = reinterpret_cast<const float4*>(g_Wlo_img);
        float4* whi = reinterpret_cast<float4*>(smem + SM_WHI);
        float4* wlo = reinterpret_cast<float4*>(smem + SM_WLO);
        #pragma unroll 4
        for (int i = tid; i < 65536 / 16; i += 256) {
            whi[i] = hi4[i];
            wlo[i] = lo4[i];
        }
    }

    // --- Fill X tile [64 rows][256 k] = [self | agg], bf16 hi/lo, swizzled ---
    {
        #pragma unroll 4
        for (int i = tid; i < 64 * 128; i += 256) {   // 128 k-pairs per row
            const int row = i >> 7;
            const int kp  = i & 127;
            const int n   = n0b + row;
            float2 x = make_float2(0.f, 0.f);
            if (n < N_NODES) {
                x = (kp < 64)
                  ? *reinterpret_cast<const float2*>(self_feat + (size_t)n * D_FEAT + kp * 2)
                  : *reinterpret_cast<const float2*>(g_agg + (size_t)n * D_FEAT + (kp - 64) * 2);
            }
            __nv_bfloat162 h, l;
            h.x = __float2bfloat16(x.x);  h.y = __float2bfloat16(x.y);
            l.x = __float2bfloat16(x.x - __bfloat162float(h.x));
            l.y = __float2bfloat16(x.y - __bfloat162float(h.y));
            const uint32_t off = swzX(row, kp * 4);
            *reinterpret_cast<__nv_bfloat162*>(smem + SM_XHI + off) = h;
            *reinterpret_cast<__nv_bfloat162*>(smem + SM_XLO + off) = l;
        }
    }
    __syncthreads();

    // Warp tile: m-rows [mrow0, mrow0+16), n-cols [ncol0, ncol0+64)
    const int mrow0 = (wid & 3) * 16;
    const int ncol0 = (wid >> 2) * 64;

    float c[8][4];
    #pragma unroll
    for (int t = 0; t < 8; ++t)
        #pragma unroll
        for (int q = 0; q < 4; ++q) c[t][q] = 0.f;

    const int sub = lane >> 3;
    const int rr  = lane & 7;

    #pragma unroll 4
    for (int ks = 0; ks < 16; ++ks) {
        // A fragment addresses: mats (m0-7,k0-7),(m8-15,k0-7),(m0-7,k8-15),(m8-15,k8-15)
        const int arow = mrow0 + rr + (sub & 1) * 8;
        const int akb  = ks * 32 + (sub >> 1) * 16;
        const uint32_t aoff = swzX(arow, akb);
        uint32_t ah[4], al[4];
        ldsm_x4(sbase + SM_XHI + aoff, ah);
        ldsm_x4(sbase + SM_XLO + aoff, al);

        // B addresses: rows k, 16B of n; mats (k0-7,n0),(k8-15,n0),(k0-7,n0+8),(k8-15,n0+8)
        const int bk = ks * 16 + rr + (sub & 1) * 8;

        #pragma unroll
        for (int np = 0; np < 4; ++np) {   // pair of n-tiles (16 cols)
            const int nb = (ncol0 + np * 16) * 2 + (sub >> 1) * 16;
            const uint32_t boff = swzW(bk, nb);
            uint32_t bh[4], bl[4];
            ldsm_x4_t(sbase + SM_WHI + boff, bh);
            ldsm_x4_t(sbase + SM_WLO + boff, bl);

            mma_16816(c[np * 2],     ah, bh[0], bh[1]);
            mma_16816(c[np * 2],     ah, bl[0], bl[1]);
            mma_16816(c[np * 2],     al, bh[0], bh[1]);
            mma_16816(c[np * 2 + 1], ah, bh[2], bh[3]);
            mma_16816(c[np * 2 + 1], ah, bl[2], bl[3]);
            mma_16816(c[np * 2 + 1], al, bh[2], bh[3]);
        }
    }

    // --- Epilogue: C frag -> out. lane l: rows lane/4 (+8), cols (lane%4)*2 ---
    const int row_lo = n0b + mrow0 + (lane >> 2);
    const int row_hi = row_lo + 8;
    const int cbase  = ncol0 + (lane & 3) * 2;
    #pragma unroll
    for (int t = 0; t < 8; ++t) {
        const int col = cbase + t * 8;
        if (row_lo < N_NODES)
            *reinterpret_cast<float2*>(out + (size_t)row_lo * OUT_DIM + col) =
                make_float2(c[t][0], c[t][1]);
        if (row_hi < N_NODES)
            *reinterpret_cast<float2*>(out + (size_t)row_hi * OUT_DIM + col) =
                make_float2(c[t][2], c[t][3]);
    }
}

// ---------------------------------------------------------------------------
// Launch
// ---------------------------------------------------------------------------
extern "C" void kernel_launch(void* const* d_in, const int* in_sizes, int n_in,
                              void* d_out, int out_size) {
    const float* self_feat = (const float*)d_in[0];
    const float* nbr_feat  = (const float*)d_in[1];
    const int*   src_idx   = (const int*)  d_in[2];
    const float* W         = (const float*)d_in[3];
    float*       out       = (float*)d_out;

    (void)in_sizes; (void)n_in; (void)out_size;

    const int nodes_blks = (N_NODES + 255) / 256;
    const int edges_blks = (N_EDGES + 255) / 256;

    zero_counters_kernel<<<nodes_blks, 256>>>();
    wconv_kernel<<<(K_DIM * OUT_DIM + 255) / 256, 256>>>(W);
    count_kernel<<<edges_blks, 256>>>(src_idx);
    scan_partial_kernel<<<N_SCAN_BLKS, SCAN_BLK>>>();
    scan_btot_kernel<<<1, 128>>>();
    scatter_ids_kernel<<<edges_blks, 256>>>(src_idx);
    gather_kernel<<<(N_NODES + 7) / 8, 256>>>(nbr_feat);

    cudaFuncSetAttribute(gemm_mma_kernel,
                         cudaFuncAttributeMaxDynamicSharedMemorySize, SM_TOT);
    gemm_mma_kernel<<<(N_NODES + 63) / 64, 256, SM_TOT>>>(self_feat, out);
}

// round 6
// speedup vs baseline: 1.2906x; 1.2906x over previous
#include <cuda_runtime.h>
#include <cuda_bf16.h>
#include <cstdint>

#define N_NODES 50000
#define N_EDGES 600000
#define D_FEAT  128
#define OUT_DIM 128
#define K_DIM   256   // 2 * D_FEAT

#define SCAN_BLK 512
#define N_SCAN_BLKS ((N_NODES + SCAN_BLK - 1) / SCAN_BLK)   // 98

// ---------------------------------------------------------------------------
// Scratch (static device globals; no allocation anywhere)
// ---------------------------------------------------------------------------
__device__ int g_cnt_i [N_NODES];
__device__ int g_cursor[N_NODES];
__device__ int g_off   [N_NODES];
__device__ int g_btot  [N_SCAN_BLKS];
__device__ int g_boff  [N_SCAN_BLKS];
__device__ int g_eid   [N_EDGES];
__device__ __align__(16) float g_agg[N_NODES * D_FEAT];   // 25.6 MB

// ---------------------------------------------------------------------------
// Kernel 1: zero counters
// ---------------------------------------------------------------------------
__global__ void zero_counters_kernel() {
    int i = blockIdx.x * blockDim.x + threadIdx.x;
    if (i < N_NODES) { g_cnt_i[i] = 0; g_cursor[i] = 0; }
}

// ---------------------------------------------------------------------------
// Kernel 2: histogram of destination nodes
// ---------------------------------------------------------------------------
__global__ void count_kernel(const int* __restrict__ src_idx) {
    int e = blockIdx.x * blockDim.x + threadIdx.x;
    if (e < N_EDGES) atomicAdd(&g_cnt_i[src_idx[e]], 1);
}

// ---------------------------------------------------------------------------
// Kernel 3: per-block exclusive scan
// ---------------------------------------------------------------------------
__global__ __launch_bounds__(SCAN_BLK)
void scan_partial_kernel() {
    __shared__ int sh[SCAN_BLK];
    const int tid = threadIdx.x;
    const int i   = blockIdx.x * SCAN_BLK + tid;
    const int v   = (i < N_NODES) ? g_cnt_i[i] : 0;
    sh[tid] = v;
    __syncthreads();
    #pragma unroll
    for (int d = 1; d < SCAN_BLK; d <<= 1) {
        int t = (tid >= d) ? sh[tid - d] : 0;
        __syncthreads();
        sh[tid] += t;
        __syncthreads();
    }
    if (i < N_NODES) g_off[i] = sh[tid] - v;   // exclusive within block
    if (tid == SCAN_BLK - 1) g_btot[blockIdx.x] = sh[tid];
}

// ---------------------------------------------------------------------------
// Kernel 4: parallel scan of the 98 block totals
// ---------------------------------------------------------------------------
__global__ __launch_bounds__(128)
void scan_btot_kernel() {
    __shared__ int sh[128];
    const int t = threadIdx.x;
    const int v = (t < N_SCAN_BLKS) ? g_btot[t] : 0;
    sh[t] = v;
    __syncthreads();
    #pragma unroll
    for (int d = 1; d < 128; d <<= 1) {
        int x = (t >= d) ? sh[t - d] : 0;
        __syncthreads();
        sh[t] += x;
        __syncthreads();
    }
    if (t < N_SCAN_BLKS) g_boff[t] = sh[t] - v;   // exclusive
}

// ---------------------------------------------------------------------------
// Kernel 5: scatter edge ids into destination-sorted order
// ---------------------------------------------------------------------------
__global__ void scatter_ids_kernel(const int* __restrict__ src_idx) {
    int e = blockIdx.x * blockDim.x + threadIdx.x;
    if (e < N_EDGES) {
        const int s = src_idx[e];
        const int pos = g_off[s] + g_boff[s >> 9] + atomicAdd(&g_cursor[s], 1);
        g_eid[pos] = e;
    }
}

// ---------------------------------------------------------------------------
// Kernel 6: gather-reduce. One warp per node; lane owns a float4 chunk.
// Edge-id pair prefetched one iteration ahead to break the eid->row
// dependent-latency chain; 2 row-loads in flight per lane.
// ---------------------------------------------------------------------------
__global__ __launch_bounds__(256)
void gather_kernel(const float* __restrict__ nbr_feat) {
    const int warp = (blockIdx.x * blockDim.x + threadIdx.x) >> 5;
    const int lane = threadIdx.x & 31;
    if (warp >= N_NODES) return;

    const int base = g_off[warp] + g_boff[warp >> 9];
    const int deg  = g_cnt_i[warp];

    const float4* nb4 = reinterpret_cast<const float4*>(nbr_feat);
    float4 acc = make_float4(0.f, 0.f, 0.f, 0.f);

    int i = 0;
    if (deg >= 2) {
        int e0 = g_eid[base];
        int e1 = g_eid[base + 1];
        for (; i + 4 <= deg; i += 2) {
            const int ne0 = g_eid[base + i + 2];      // prefetch next pair
            const int ne1 = g_eid[base + i + 3];
            const float4 v0 = nb4[(size_t)e0 * (D_FEAT / 4) + lane];
            const float4 v1 = nb4[(size_t)e1 * (D_FEAT / 4) + lane];
            acc.x += v0.x + v1.x;  acc.y += v0.y + v1.y;
            acc.z += v0.z + v1.z;  acc.w += v0.w + v1.w;
            e0 = ne0; e1 = ne1;
        }
        const float4 v0 = nb4[(size_t)e0 * (D_FEAT / 4) + lane];
        const float4 v1 = nb4[(size_t)e1 * (D_FEAT / 4) + lane];
        acc.x += v0.x + v1.x;  acc.y += v0.y + v1.y;
        acc.z += v0.z + v1.z;  acc.w += v0.w + v1.w;
        i += 2;
    }
    for (; i < deg; ++i) {
        const int e = g_eid[base + i];
        const float4 v = nb4[(size_t)e * (D_FEAT / 4) + lane];
        acc.x += v.x; acc.y += v.y; acc.z += v.z; acc.w += v.w;
    }

    const float s = (deg > 0) ? (1.0f / (float)deg) : 0.0f;
    acc.x *= s; acc.y *= s; acc.z *= s; acc.w *= s;
    reinterpret_cast<float4*>(g_agg)[(size_t)warp * (D_FEAT / 4) + lane] = acc;
}

// ---------------------------------------------------------------------------
// Kernel 7: fused concat + GEMM with packed fma.rn.f32x2, K processed in two
// halves so smem = 64KB (W half) + 32KB (X half) = 96KB -> 2 CTAs/SM
// (prologue of one block overlaps the FMA stream of the other).
//   half 0: x = self_feat, W rows [0,128)
//   half 1: x = g_agg,     W rows [128,256)
// Thread t: cols j0=(t%32)*4, rows r0=(t/32)*8; 8x4 fp32 accumulators.
// ---------------------------------------------------------------------------
#define BM   64
#define TPB  256
#define KH   128                                    // K half
#define GEMM_SMEM ((KH * OUT_DIM + BM * KH) * 4)    // 65536 + 32768 = 98304 B

__global__ __launch_bounds__(TPB, 2)
void gemm_kernel(const float* __restrict__ self_feat,
                 const float* __restrict__ W,
                 float*       __restrict__ out) {
    extern __shared__ float sh[];
    float* Wsh = sh;                 // [KH][OUT_DIM]
    float* Xsh = sh + KH * OUT_DIM;  // [BM][KH]

    const int tid = threadIdx.x;
    const int n0  = blockIdx.x * BM;

    const int j0 = (tid & 31) * 4;   // output column base
    const int r0 = (tid >> 5) * 8;   // row base within tile

    unsigned long long a01[8], a23[8];
    #pragma unroll
    for (int r = 0; r < 8; ++r) { a01[r] = 0ull; a23[r] = 0ull; }

    #pragma unroll
    for (int half = 0; half < 2; ++half) {
        const float* xsrc = (half == 0) ? self_feat : g_agg;

        if (half == 1) __syncthreads();   // protect smem reuse

        // Load W half into smem (4096 float4 / 256 threads = 16 each)
        {
            const float4* W4 = reinterpret_cast<const float4*>(W + half * KH * OUT_DIM);
            float4* Wsh4 = reinterpret_cast<float4*>(Wsh);
            #pragma unroll
            for (int i = tid; i < KH * OUT_DIM / 4; i += TPB) Wsh4[i] = W4[i];
        }
        // Load X half (rows n0..n0+63, k-half columns)
        {
            const float4* x4 = reinterpret_cast<const float4*>(xsrc);
            const float4  z  = make_float4(0.f, 0.f, 0.f, 0.f);
            #pragma unroll
            for (int i = tid; i < BM * (KH / 4); i += TPB) {
                const int r  = i / (KH / 4);
                const int c4 = i % (KH / 4);
                const int n  = n0 + r;
                float4 v = z;
                if (n < N_NODES) v = x4[(size_t)n * (D_FEAT / 4) + c4];
                reinterpret_cast<float4*>(&Xsh[r * KH])[c4] = v;
            }
        }
        __syncthreads();

        #pragma unroll 2
        for (int k = 0; k < KH; k += 2) {
            const unsigned long long wA0 =
                *reinterpret_cast<const unsigned long long*>(&Wsh[k * OUT_DIM + j0]);
            const unsigned long long wB0 =
                *reinterpret_cast<const unsigned long long*>(&Wsh[k * OUT_DIM + j0 + 2]);
            const unsigned long long wA1 =
                *reinterpret_cast<const unsigned long long*>(&Wsh[(k + 1) * OUT_DIM + j0]);
            const unsigned long long wB1 =
                *reinterpret_cast<const unsigned long long*>(&Wsh[(k + 1) * OUT_DIM + j0 + 2]);

            #pragma unroll
            for (int r = 0; r < 8; ++r) {
                const float2 x = *reinterpret_cast<const float2*>(&Xsh[(r0 + r) * KH + k]);
                unsigned long long xx0, xx1;
                asm("mov.b64 %0, {%1, %1};" : "=l"(xx0) : "f"(x.x));
                asm("mov.b64 %0, {%1, %1};" : "=l"(xx1) : "f"(x.y));
                asm("fma.rn.f32x2 %0, %1, %2, %0;" : "+l"(a01[r]) : "l"(xx0), "l"(wA0));
                asm("fma.rn.f32x2 %0, %1, %2, %0;" : "+l"(a23[r]) : "l"(xx0), "l"(wB0));
                asm("fma.rn.f32x2 %0, %1, %2, %0;" : "+l"(a01[r]) : "l"(xx1), "l"(wA1));
                asm("fma.rn.f32x2 %0, %1, %2, %0;" : "+l"(a23[r]) : "l"(xx1), "l"(wB1));
            }
        }
    }

    #pragma unroll
    for (int r = 0; r < 8; ++r) {
        const int n = n0 + r0 + r;
        if (n < N_NODES) {
            float o0, o1, o2, o3;
            asm("mov.b64 {%0, %1}, %2;" : "=f"(o0), "=f"(o1) : "l"(a01[r]));
            asm("mov.b64 {%0, %1}, %2;" : "=f"(o2), "=f"(o3) : "l"(a23[r]));
            *reinterpret_cast<float4*>(&out[(size_t)n * OUT_DIM + j0]) =
                make_float4(o0, o1, o2, o3);
        }
    }
}

// ---------------------------------------------------------------------------
// Launch — exactly 7 kernels; gather is launch #6 so ncu (-s 5 -c 1)
// captures it instead of a trivial scan kernel.
// ---------------------------------------------------------------------------
extern "C" void kernel_launch(void* const* d_in, const int* in_sizes, int n_in,
                              void* d_out, int out_size) {
    const float* self_feat = (const float*)d_in[0];
    const float* nbr_feat  = (const float*)d_in[1];
    const int*   src_idx   = (const int*)  d_in[2];
    const float* W         = (const float*)d_in[3];
    float*       out       = (float*)d_out;

    (void)in_sizes; (void)n_in; (void)out_size;

    const int nodes_blks = (N_NODES + 255) / 256;
    const int edges_blks = (N_EDGES + 255) / 256;

    zero_counters_kernel<<<nodes_blks, 256>>>();                 // 1
    count_kernel<<<edges_blks, 256>>>(src_idx);                  // 2
    scan_partial_kernel<<<N_SCAN_BLKS, SCAN_BLK>>>();            // 3
    scan_btot_kernel<<<1, 128>>>();                              // 4
    scatter_ids_kernel<<<edges_blks, 256>>>(src_idx);            // 5
    gather_kernel<<<(N_NODES + 7) / 8, 256>>>(nbr_feat);         // 6  <- profiled

    cudaFuncSetAttribute(gemm_kernel,
                         cudaFuncAttributeMaxDynamicSharedMemorySize, GEMM_SMEM);
    gemm_kernel<<<(N_NODES + BM - 1) / BM, TPB, GEMM_SMEM>>>(self_feat, W, out);  // 7
}